// round 9
// baseline (speedup 1.0000x reference)
#include <cuda_runtime.h>
#include <cstdint>

#define N_PTS     4096
#define N_QUERY   (64 * 552)     // 35328
#define NSAMPLE   32
#define FEAT_D    32
#define FEAT_H    64
#define K_KEYPTS  64
#define RADIUS2   4.0f
#define OUT_GROUP_OFF (K_KEYPTS * 6)
#define FULL 0xffffffffu
#define N_TILES   128            // 4096 / 32
#define N_CELLS   4096           // 16^3 Morton cells
#define UMAX      0xFFFFFFFFu

// ---------------- device scratch (no allocs allowed) ----------------
__device__ float  g_feat[N_PTS * FEAT_D];   // tgt features (original index order)
__device__ float  g_z[N_PTS];               // src pre-softplus scores
__device__ float4 g_sp[N_PTS];              // Morton-sorted tgt xyz + ||p||^2
__device__ int    g_sidx[N_PTS];            // permuted -> original index
__device__ float4 g_tile[N_TILES];          // per-tile center (xyz) + inflated radius (w)
__device__ int    g_mort[N_PTS];            // scratch: morton code per point
__device__ int    g_pos0;                   // permuted position of original index 0

__device__ __forceinline__ int morton12(int ix, int iy, int iz)
{
    int m = 0;
#pragma unroll
    for (int b = 0; b < 4; b++) {
        m |= ((ix >> b) & 1) << (3 * b + 2);
        m |= ((iy >> b) & 1) << (3 * b + 1);
        m |= ((iz >> b) & 1) << (3 * b + 0);
    }
    return m;
}

// ---------------- Kernel 1: fused MLP (blocks 0-7) + Morton sort/stats (block 8) ----------------
__global__ void __launch_bounds__(1024) pre_kernel(
    const float* __restrict__ src, const float* __restrict__ tgt,
    const float* __restrict__ W1, const float* __restrict__ b1,
    const float* __restrict__ W2, const float* __restrict__ b2,
    const float* __restrict__ Wq, const float* __restrict__ bq)
{
    __shared__ float sW1[FEAT_H * 6], sb1[FEAT_H];
    __shared__ float sW2[FEAT_D * FEAT_H], sb2[FEAT_D], sWq[FEAT_D];
    __shared__ int sh_hist[N_CELLS];
    __shared__ int sh_wsum[32];
    int tid = threadIdx.x;
    int b = blockIdx.x;

    if (b < 8) {
        // ===== MLP: blocks 0-3 = src (scores), blocks 4-7 = tgt (features) =====
        for (int i = tid; i < FEAT_H * 6; i += 1024) sW1[i] = W1[i];
        if (tid < FEAT_H) sb1[tid] = b1[tid];
        for (int i = tid; i < FEAT_D * FEAT_H; i += 1024) sW2[i] = W2[i];
        if (tid < FEAT_D) { sb2[tid] = b2[tid]; sWq[tid] = Wq[tid]; }
        __syncthreads();

        bool is_tgt = (b >= 4);
        int n = (b & 3) * 1024 + tid;
        const float* pts = is_tgt ? tgt : src;

        float p[6];
#pragma unroll
        for (int c = 0; c < 6; c++) p[c] = pts[c * N_PTS + n];

        float facc[FEAT_D];
#pragma unroll
        for (int f = 0; f < FEAT_D; f++) facc[f] = 0.0f;

        for (int o = 0; o < FEAT_H; o++) {
            float a = 0.0f;
#pragma unroll
            for (int c = 0; c < 6; c++) a = fmaf(sW1[o * 6 + c], p[c], a);
            a += sb1[o];
            float h = fmaxf(a, 0.0f);
#pragma unroll
            for (int f = 0; f < FEAT_D; f++) facc[f] = fmaf(sW2[f * FEAT_H + o], h, facc[f]);
        }

        if (is_tgt) {
#pragma unroll
            for (int f = 0; f < FEAT_D; f++) {
                float v = fmaxf(facc[f] + sb2[f], 0.0f);
                g_feat[n * FEAT_D + f] = v;
            }
        } else {
            float z = 0.0f;
#pragma unroll
            for (int f = 0; f < FEAT_D; f++) {
                float v = fmaxf(facc[f] + sb2[f], 0.0f);
                z = fmaf(sWq[f], v, z);
            }
            z += bq[0];
            g_z[n] = z;   // softplus is monotonic -> rank on pre-activation
        }
        return;
    }

    // ===== block 8: Morton counting-sort of tgt + tile stats =====
    int t = tid;
    for (int i = t; i < N_CELLS; i += 1024) sh_hist[i] = 0;
    __syncthreads();

    for (int i = t; i < N_PTS; i += 1024) {
        float x = tgt[i], y = tgt[N_PTS + i], z = tgt[2 * N_PTS + i];
        int ix = min(15, max(0, (int)floorf((x + 5.0f) * 1.6f)));
        int iy = min(15, max(0, (int)floorf((y + 5.0f) * 1.6f)));
        int iz = min(15, max(0, (int)floorf((z + 5.0f) * 1.6f)));
        int mm = morton12(ix, iy, iz);
        g_mort[i] = mm;
        atomicAdd(&sh_hist[mm], 1);
    }
    __syncthreads();

    int c0 = sh_hist[4 * t], c1 = sh_hist[4 * t + 1], c2 = sh_hist[4 * t + 2], c3 = sh_hist[4 * t + 3];
    int tsum = c0 + c1 + c2 + c3;
    int lane = t & 31, wid = t >> 5;
    int inc = tsum;
#pragma unroll
    for (int d = 1; d < 32; d <<= 1) { int y = __shfl_up_sync(FULL, inc, d); if (lane >= d) inc += y; }
    if (lane == 31) sh_wsum[wid] = inc;
    __syncthreads();
    if (t < 32) {
        int v = sh_wsum[t]; int w = v;
#pragma unroll
        for (int d = 1; d < 32; d <<= 1) { int y = __shfl_up_sync(FULL, w, d); if (t >= d) w += y; }
        sh_wsum[t] = w - v;
    }
    __syncthreads();
    int base = (inc - tsum) + sh_wsum[wid];
    sh_hist[4 * t]     = base;
    sh_hist[4 * t + 1] = base + c0;
    sh_hist[4 * t + 2] = base + c0 + c1;
    sh_hist[4 * t + 3] = base + c0 + c1 + c2;
    __syncthreads();

    for (int i = t; i < N_PTS; i += 1024) {
        float x = tgt[i], y = tgt[N_PTS + i], z = tgt[2 * N_PTS + i];
        int mm = g_mort[i];
        int pos = atomicAdd(&sh_hist[mm], 1);
        float pp = __fadd_rn(__fadd_rn(__fmul_rn(x, x), __fmul_rn(y, y)), __fmul_rn(z, z));
        g_sp[pos]   = make_float4(x, y, z, pp);
        g_sidx[pos] = i;
        if (i == 0) g_pos0 = pos;
    }
    __syncthreads();

    if (t < N_TILES) {
        float mnx = 1e30f, mny = 1e30f, mnz = 1e30f;
        float mxx = -1e30f, mxy = -1e30f, mxz = -1e30f;
        for (int j = 0; j < 32; j++) {
            float4 P = g_sp[t * 32 + j];
            mnx = fminf(mnx, P.x); mxx = fmaxf(mxx, P.x);
            mny = fminf(mny, P.y); mxy = fmaxf(mxy, P.y);
            mnz = fminf(mnz, P.z); mxz = fmaxf(mxz, P.z);
        }
        float cx = (mnx + mxx) * 0.5f, cy = (mny + mxy) * 0.5f, cz = (mnz + mxz) * 0.5f;
        float maxd2 = 0.0f;
        for (int j = 0; j < 32; j++) {
            float4 P = g_sp[t * 32 + j];
            float dx = P.x - cx, dy = P.y - cy, dz = P.z - cz;
            maxd2 = fmaxf(maxd2, dx * dx + dy * dy + dz * dz);
        }
        float rt = sqrtf(maxd2) * 1.0001f + 1e-5f;   // inflate => bound underestimates => safe
        g_tile[t] = make_float4(cx, cy, cz, rt);
    }
}

// ---------------- tile processing: total-order (dist_bits, orig_idx) selection ----------------
__device__ __forceinline__ void process_tile(
    int t, int lane, float qx, float qy, float qz, float qq,
    const float4* __restrict__ sp, const unsigned short* __restrict__ sidx,
    unsigned& bu, unsigned& bo, int& bi, unsigned& thr_u, unsigned& thr_o)
{
    float4 P = sp[t * 32 + lane];
    float dot = fmaf(qz, P.z, fmaf(qy, P.y, __fmul_rn(qx, P.x)));
    float sq  = __fadd_rn(__fsub_rn(qq, __fmul_rn(2.0f, dot)), P.w);
    unsigned u = __float_as_uint(sq);
    u = (u & 0x80000000u) ? ~u : (u | 0x80000000u);  // monotone total order on floats
    unsigned orig = (unsigned)sidx[t * 32 + lane];

    bool ok = (sq <= RADIUS2) && ((u < thr_u) || (u == thr_u && orig < thr_o));
    unsigned mask = __ballot_sync(FULL, ok);
    while (mask) {
        int s = __ffs(mask) - 1;
        mask &= mask - 1;
        unsigned uc = __shfl_sync(FULL, u, s);
        unsigned oc = __shfl_sync(FULL, orig, s);
        if ((uc < thr_u) || (uc == thr_u && oc < thr_o)) {   // warp-uniform
            int ic = t * 32 + s;
            unsigned pu = __shfl_up_sync(FULL, bu, 1);
            unsigned po = __shfl_up_sync(FULL, bo, 1);
            int      pi = __shfl_up_sync(FULL, bi, 1);
            bool cand_lt_mine = (uc < bu) || (uc == bu && oc < bo);
            if (cand_lt_mine) {                               // shift-insert; lane 31 falls off
                // take candidate where predecessor <= candidate (insertion point);
                // faithful split-word version of the proven 64-bit `pk <= kc`
                bool pred_le_cand = (pu < uc) || (pu == uc && po <= oc);
                bool take = (lane == 0) || pred_le_cand;
                bu = take ? uc : pu;
                bo = take ? oc : po;
                bi = take ? ic : pi;
            }
            thr_u = __shfl_sync(FULL, bu, 31);
            thr_o = __shfl_sync(FULL, bo, 31);
        }
    }
}

// ---------------- Kernel 2: topk (block 0) + ball-query nearest-32 + gather ----------------
__global__ void __launch_bounds__(512)
group_kernel(const float* __restrict__ cand, const float* __restrict__ src_pts,
             float* __restrict__ out)
{
    extern __shared__ char dynsmem[];
    int tid = threadIdx.x;

    if (blockIdx.x == 0) {
        // ===== top-64 of src scores -> src_keypts (overlapped with group blocks) =====
        unsigned long long* skey = (unsigned long long*)dynsmem;
        __shared__ unsigned long long warpmax[16];
        __shared__ int sel[K_KEYPTS];

        for (int i = tid; i < N_PTS; i += 512) {
            float z = g_z[i];
            unsigned u = __float_as_uint(z);
            u = (u & 0x80000000u) ? ~u : (u | 0x80000000u);
            skey[i] = ((unsigned long long)u << 32) | (unsigned long long)(0xFFFFFFFFu - (unsigned)i);
        }
        __syncthreads();

        for (int k = 0; k < K_KEYPTS; k++) {
            unsigned long long best = 0ull;
            for (int i = tid; i < N_PTS; i += 512) {
                unsigned long long v = skey[i];
                best = (v > best) ? v : best;
            }
#pragma unroll
            for (int off = 16; off; off >>= 1) {
                unsigned long long o = __shfl_xor_sync(FULL, best, off);
                best = (o > best) ? o : best;
            }
            if ((tid & 31) == 0) warpmax[tid >> 5] = best;
            __syncthreads();
            if (tid == 0) {
                unsigned long long bb = warpmax[0];
                for (int w = 1; w < 16; w++) bb = (warpmax[w] > bb) ? warpmax[w] : bb;
                int idx = (int)(0xFFFFFFFFu - (unsigned)(bb & 0xFFFFFFFFull));
                sel[k] = idx;
                skey[idx] = 0ull;
            }
            __syncthreads();
        }
        if (tid < K_KEYPTS * 6) {
            int k = tid / 6, c = tid % 6;
            out[k * 6 + c] = src_pts[c * N_PTS + sel[k]];
        }
        return;
    }

    // ===== group blocks =====
    float4* sp            = (float4*)dynsmem;                              // 64KB
    unsigned short* sidx  = (unsigned short*)(dynsmem + 65536);            // 8KB
    float4* stile         = (float4*)(dynsmem + 65536 + 8192);             // 2KB

    for (int i = tid; i < N_PTS; i += 512) { sp[i] = g_sp[i]; sidx[i] = (unsigned short)g_sidx[i]; }
    for (int i = tid; i < N_TILES; i += 512) stile[i] = g_tile[i];
    __syncthreads();

    int warp = tid >> 5;
    int lane = tid & 31;
    int m = (blockIdx.x - 1) * 16 + warp;    // 2208 * 16 == 35328

    float qx = cand[m * 3 + 0];
    float qy = cand[m * 3 + 1];
    float qz = cand[m * 3 + 2];
    float qq = __fadd_rn(__fadd_rn(__fmul_rn(qx, qx), __fmul_rn(qy, qy)), __fmul_rn(qz, qz));

    // ---- per-tile conservative lower bounds, lane-parallel (4 tiles per lane) ----
    unsigned key[4];
#pragma unroll
    for (int r = 0; r < 4; r++) {
        int t = r * 32 + lane;
        float4 T = stile[t];
        float dx = qx - T.x, dy = qy - T.y, dz = qz - T.z;
        float dc = sqrtf(dx * dx + dy * dy + dz * dz);
        float b  = fmaxf(dc - T.w, 0.0f);
        float bnd = b * b;
        // truncate low 8 mantissa bits (rounds DOWN for +floats => conservative)
        key[r] = (__float_as_uint(bnd) & 0xFFFFFF00u) | (unsigned)t;
    }

    // ---- top-32 state: lane-sorted ascending (dist_bits, orig_idx); lane 31 = worst ----
    unsigned bu = UMAX, bo = UMAX; int bi = 0;
    unsigned thr_u = UMAX, thr_o = UMAX;

    // ---- seed: process the 2 minimum-bound tiles to tighten thr fast ----
#pragma unroll
    for (int sd = 0; sd < 2; sd++) {
        unsigned mn = min(min(key[0], key[1]), min(key[2], key[3]));
#pragma unroll
        for (int off = 16; off; off >>= 1) mn = min(mn, __shfl_xor_sync(FULL, mn, off));
        process_tile((int)(mn & 0xFFu), lane, qx, qy, qz, qq, sp, sidx, bu, bo, bi, thr_u, thr_o);
#pragma unroll
        for (int r = 0; r < 4; r++) if (key[r] == mn) key[r] = UMAX;
    }

    // ---- rounds: ballot pass-mask vs current threshold; process set bits only ----
    // Correct for ANY visit order: a tile is skipped only when its conservative bound
    // exceeds min(thr,R2)+0.01 (margin >> expanded-formula error); thr only tightens.
#pragma unroll
    for (int r = 0; r < 4; r++) {
        while (true) {
            float thr_d = __uint_as_float((thr_u & 0x80000000u) ? (thr_u ^ 0x80000000u) : ~thr_u);
            float limit = fminf(thr_d, RADIUS2) + 0.01f;     // fminf(NaN,R2)=R2 when not full
            float mybnd = __uint_as_float(key[r] & 0xFFFFFF00u);  // UMAX -> NaN -> pass=false
            bool pass = (mybnd <= limit);
            unsigned msk = __ballot_sync(FULL, pass);
            if (!msk) break;
            int s = __ffs(msk) - 1;
            unsigned kk = __shfl_sync(FULL, key[r], s);
            if (lane == s) key[r] = UMAX;                    // mark processed
            process_tile((int)(kk & 0xFFu), lane, qx, qy, qz, qq, sp, sidx, bu, bo, bi, thr_u, thr_o);
        }
    }

    // padding: invalid slots take slot-0's index; if no valid neighbor -> original index 0
    int nv  = __popc(__ballot_sync(FULL, bu != UMAX));   // admitted => sq <= RADIUS2
    int bi0 = __shfl_sync(FULL, bi, 0);
    int fidx;
    if (nv > 0) {
        fidx = (lane < nv) ? bi : bi0;
    } else {
        fidx = g_pos0;                 // permuted position of original point 0
    }

    // coalesced write of 32*35 = 1120 floats per query
    float* op = out + OUT_GROUP_OFF + (size_t)m * (NSAMPLE * 35);
    int slot = 0, t35 = lane;
#pragma unroll 1
    for (int it = 0; it < 35; it++) {
        int is = __shfl_sync(FULL, fidx, slot);
        float val;
        if (t35 < 3) {
            float4 P = sp[is];
            float pc = (t35 == 0) ? P.x : ((t35 == 1) ? P.y : P.z);
            float qc = (t35 == 0) ? qx  : ((t35 == 1) ? qy  : qz);
            val = __fsub_rn(pc, qc);
        } else {
            int orig = (int)sidx[is];
            val = g_feat[orig * FEAT_D + (t35 - 3)];
        }
        op[it * 32 + lane] = val;
        t35 += 32;
        if (t35 >= 35) { t35 -= 35; slot++; }
    }
}

// ---------------- launch ----------------
extern "C" void kernel_launch(void* const* d_in, const int* in_sizes, int n_in,
                              void* d_out, int out_size)
{
    const float* src  = (const float*)d_in[0];
    const float* tgt  = (const float*)d_in[1];
    const float* cand = (const float*)d_in[2];
    const float* W1   = (const float*)d_in[3];
    const float* b1   = (const float*)d_in[4];
    const float* W2   = (const float*)d_in[5];
    const float* b2   = (const float*)d_in[6];
    const float* Wq   = (const float*)d_in[7];
    const float* bq   = (const float*)d_in[8];
    float* out = (float*)d_out;

    const int GROUP_SMEM = 65536 + 8192 + 2048;   // 75776

    static bool s_attr_done = false;
    if (!s_attr_done) {
        cudaFuncSetAttribute(group_kernel, cudaFuncAttributeMaxDynamicSharedMemorySize, GROUP_SMEM);
        s_attr_done = true;
    }

    pre_kernel<<<9, 1024>>>(src, tgt, W1, b1, W2, b2, Wq, bq);
    group_kernel<<<1 + N_QUERY / 16, 512, GROUP_SMEM>>>(cand, src, out);
}

// round 10
// speedup vs baseline: 1.5502x; 1.5502x over previous
#include <cuda_runtime.h>
#include <cstdint>

#define N_PTS     4096
#define N_QUERY   (64 * 552)     // 35328
#define NSAMPLE   32
#define FEAT_D    32
#define FEAT_H    64
#define K_KEYPTS  64
#define RADIUS2   4.0f
#define OUT_GROUP_OFF (K_KEYPTS * 6)
#define FULL 0xffffffffu
#define N_TILES   128            // 4096 / 32
#define N_CELLS   4096           // 16^3 Morton cells
#define UMAX      0xFFFFFFFFu

// ---------------- device scratch (no allocs allowed) ----------------
__device__ float  g_feat[N_PTS * FEAT_D];   // tgt features (original index order)
__device__ float  g_z[N_PTS];               // src pre-softplus scores
__device__ float4 g_sp[N_PTS];              // Morton-sorted tgt xyz + ||p||^2
__device__ int    g_sidx[N_PTS];            // permuted -> original index
__device__ float4 g_tile[N_TILES];          // per-tile center (xyz) + inflated radius (w)
__device__ int    g_mort[N_PTS];            // scratch: morton code per point
__device__ int    g_pos0;                   // permuted position of original index 0

__device__ __forceinline__ int morton12(int ix, int iy, int iz)
{
    int m = 0;
#pragma unroll
    for (int b = 0; b < 4; b++) {
        m |= ((ix >> b) & 1) << (3 * b + 2);
        m |= ((iy >> b) & 1) << (3 * b + 1);
        m |= ((iz >> b) & 1) << (3 * b + 0);
    }
    return m;
}

// ---------------- Kernel 1: fused MLP (blocks 0-7) + Morton sort/stats (block 8) ----------------
__global__ void __launch_bounds__(1024) pre_kernel(
    const float* __restrict__ src, const float* __restrict__ tgt,
    const float* __restrict__ W1, const float* __restrict__ b1,
    const float* __restrict__ W2, const float* __restrict__ b2,
    const float* __restrict__ Wq, const float* __restrict__ bq)
{
    __shared__ float sW1[FEAT_H * 6], sb1[FEAT_H];
    __shared__ float sW2[FEAT_D * FEAT_H], sb2[FEAT_D], sWq[FEAT_D];
    __shared__ int sh_hist[N_CELLS];
    __shared__ int sh_wsum[32];
    int tid = threadIdx.x;
    int b = blockIdx.x;

    if (b < 8) {
        // ===== MLP: blocks 0-3 = src (scores), blocks 4-7 = tgt (features) =====
        for (int i = tid; i < FEAT_H * 6; i += 1024) sW1[i] = W1[i];
        if (tid < FEAT_H) sb1[tid] = b1[tid];
        for (int i = tid; i < FEAT_D * FEAT_H; i += 1024) sW2[i] = W2[i];
        if (tid < FEAT_D) { sb2[tid] = b2[tid]; sWq[tid] = Wq[tid]; }
        __syncthreads();

        bool is_tgt = (b >= 4);
        int n = (b & 3) * 1024 + tid;
        const float* pts = is_tgt ? tgt : src;

        float p[6];
#pragma unroll
        for (int c = 0; c < 6; c++) p[c] = pts[c * N_PTS + n];

        float facc[FEAT_D];
#pragma unroll
        for (int f = 0; f < FEAT_D; f++) facc[f] = 0.0f;

        for (int o = 0; o < FEAT_H; o++) {
            float a = 0.0f;
#pragma unroll
            for (int c = 0; c < 6; c++) a = fmaf(sW1[o * 6 + c], p[c], a);
            a += sb1[o];
            float h = fmaxf(a, 0.0f);
#pragma unroll
            for (int f = 0; f < FEAT_D; f++) facc[f] = fmaf(sW2[f * FEAT_H + o], h, facc[f]);
        }

        if (is_tgt) {
#pragma unroll
            for (int f = 0; f < FEAT_D; f++) {
                float v = fmaxf(facc[f] + sb2[f], 0.0f);
                g_feat[n * FEAT_D + f] = v;
            }
        } else {
            float z = 0.0f;
#pragma unroll
            for (int f = 0; f < FEAT_D; f++) {
                float v = fmaxf(facc[f] + sb2[f], 0.0f);
                z = fmaf(sWq[f], v, z);
            }
            z += bq[0];
            g_z[n] = z;   // softplus is monotonic -> rank on pre-activation
        }
        return;
    }

    // ===== block 8: Morton counting-sort of tgt + tile stats =====
    int t = tid;
    for (int i = t; i < N_CELLS; i += 1024) sh_hist[i] = 0;
    __syncthreads();

    for (int i = t; i < N_PTS; i += 1024) {
        float x = tgt[i], y = tgt[N_PTS + i], z = tgt[2 * N_PTS + i];
        int ix = min(15, max(0, (int)floorf((x + 5.0f) * 1.6f)));
        int iy = min(15, max(0, (int)floorf((y + 5.0f) * 1.6f)));
        int iz = min(15, max(0, (int)floorf((z + 5.0f) * 1.6f)));
        int mm = morton12(ix, iy, iz);
        g_mort[i] = mm;
        atomicAdd(&sh_hist[mm], 1);
    }
    __syncthreads();

    int c0 = sh_hist[4 * t], c1 = sh_hist[4 * t + 1], c2 = sh_hist[4 * t + 2], c3 = sh_hist[4 * t + 3];
    int tsum = c0 + c1 + c2 + c3;
    int lane = t & 31, wid = t >> 5;
    int inc = tsum;
#pragma unroll
    for (int d = 1; d < 32; d <<= 1) { int y = __shfl_up_sync(FULL, inc, d); if (lane >= d) inc += y; }
    if (lane == 31) sh_wsum[wid] = inc;
    __syncthreads();
    if (t < 32) {
        int v = sh_wsum[t]; int w = v;
#pragma unroll
        for (int d = 1; d < 32; d <<= 1) { int y = __shfl_up_sync(FULL, w, d); if (t >= d) w += y; }
        sh_wsum[t] = w - v;
    }
    __syncthreads();
    int base = (inc - tsum) + sh_wsum[wid];
    sh_hist[4 * t]     = base;
    sh_hist[4 * t + 1] = base + c0;
    sh_hist[4 * t + 2] = base + c0 + c1;
    sh_hist[4 * t + 3] = base + c0 + c1 + c2;
    __syncthreads();

    for (int i = t; i < N_PTS; i += 1024) {
        float x = tgt[i], y = tgt[N_PTS + i], z = tgt[2 * N_PTS + i];
        int mm = g_mort[i];
        int pos = atomicAdd(&sh_hist[mm], 1);
        float pp = __fadd_rn(__fadd_rn(__fmul_rn(x, x), __fmul_rn(y, y)), __fmul_rn(z, z));
        g_sp[pos]   = make_float4(x, y, z, pp);
        g_sidx[pos] = i;
        if (i == 0) g_pos0 = pos;
    }
    __syncthreads();

    if (t < N_TILES) {
        float mnx = 1e30f, mny = 1e30f, mnz = 1e30f;
        float mxx = -1e30f, mxy = -1e30f, mxz = -1e30f;
        for (int j = 0; j < 32; j++) {
            float4 P = g_sp[t * 32 + j];
            mnx = fminf(mnx, P.x); mxx = fmaxf(mxx, P.x);
            mny = fminf(mny, P.y); mxy = fmaxf(mxy, P.y);
            mnz = fminf(mnz, P.z); mxz = fmaxf(mxz, P.z);
        }
        float cx = (mnx + mxx) * 0.5f, cy = (mny + mxy) * 0.5f, cz = (mnz + mxz) * 0.5f;
        float maxd2 = 0.0f;
        for (int j = 0; j < 32; j++) {
            float4 P = g_sp[t * 32 + j];
            float dx = P.x - cx, dy = P.y - cy, dz = P.z - cz;
            maxd2 = fmaxf(maxd2, dx * dx + dy * dy + dz * dz);
        }
        float rt = sqrtf(maxd2) * 1.0001f + 1e-5f;   // inflate => bound underestimates => safe
        g_tile[t] = make_float4(cx, cy, cz, rt);
    }
}

// ---------------- candidate key for a lane: (orderable dist bits, orig idx) ----------------
__device__ __forceinline__ void make_cand(
    int t, int lane, float qx, float qy, float qz, float qq,
    const float4* __restrict__ sp, const unsigned short* __restrict__ sidx,
    float& sq, unsigned& u, unsigned& o)
{
    float4 P = sp[t * 32 + lane];
    float dot = fmaf(qz, P.z, fmaf(qy, P.y, __fmul_rn(qx, P.x)));
    sq = __fadd_rn(__fsub_rn(qq, __fmul_rn(2.0f, dot)), P.w);
    u = __float_as_uint(sq);
    u = (u & 0x80000000u) ? ~u : (u | 0x80000000u);  // monotone total order on floats
    o = (unsigned)sidx[t * 32 + lane];
}

// ---------------- seed: bitonic-sort the first tile's 32 candidates into the list ----------------
__device__ __forceinline__ void seed_tile(
    int t, int lane, float qx, float qy, float qz, float qq,
    const float4* __restrict__ sp, const unsigned short* __restrict__ sidx,
    unsigned& bu, unsigned& bo, int& bi, unsigned& thr_u, unsigned& thr_o)
{
    float sq; unsigned u, o;
    make_cand(t, lane, qx, qy, qz, qq, sp, sidx, sq, u, o);
    if (!(sq <= RADIUS2)) { u = UMAX; o = UMAX; }   // sentinel; sorts to top
    int i = t * 32 + lane;

    // bitonic sort ascending by (u,o) across 32 lanes (equal keys only among sentinels)
#pragma unroll
    for (int k = 2; k <= 32; k <<= 1) {
#pragma unroll
        for (int j = k >> 1; j > 0; j >>= 1) {
            unsigned u2 = __shfl_xor_sync(FULL, u, j);
            unsigned o2 = __shfl_xor_sync(FULL, o, j);
            int      i2 = __shfl_xor_sync(FULL, i, j);
            bool up    = ((lane & k) == 0);          // k=32: always true -> ascending
            bool isLow = ((lane & j) == 0);
            bool theirs_lt = (u2 < u) || (u2 == u && o2 < o);
            bool takeTheirs = (isLow == up) ? theirs_lt : !theirs_lt;
            if (takeTheirs) { u = u2; o = o2; i = i2; }
        }
    }
    bu = u; bo = o; bi = i;
    thr_u = __shfl_sync(FULL, bu, 31);
    thr_o = __shfl_sync(FULL, bo, 31);
}

// ---------------- tile processing: total-order (dist_bits, orig_idx) selection ----------------
// (verbatim from R9 — verified bit-exact vs the full scan)
__device__ __forceinline__ void process_tile(
    int t, int lane, float qx, float qy, float qz, float qq,
    const float4* __restrict__ sp, const unsigned short* __restrict__ sidx,
    unsigned& bu, unsigned& bo, int& bi, unsigned& thr_u, unsigned& thr_o)
{
    float sq; unsigned u, orig;
    make_cand(t, lane, qx, qy, qz, qq, sp, sidx, sq, u, orig);

    bool ok = (sq <= RADIUS2) && ((u < thr_u) || (u == thr_u && orig < thr_o));
    unsigned mask = __ballot_sync(FULL, ok);
    while (mask) {
        int s = __ffs(mask) - 1;
        mask &= mask - 1;
        unsigned uc = __shfl_sync(FULL, u, s);
        unsigned oc = __shfl_sync(FULL, orig, s);
        if ((uc < thr_u) || (uc == thr_u && oc < thr_o)) {   // warp-uniform
            int ic = t * 32 + s;
            unsigned pu = __shfl_up_sync(FULL, bu, 1);
            unsigned po = __shfl_up_sync(FULL, bo, 1);
            int      pi = __shfl_up_sync(FULL, bi, 1);
            bool cand_lt_mine = (uc < bu) || (uc == bu && oc < bo);
            if (cand_lt_mine) {                               // shift-insert; lane 31 falls off
                bool pred_le_cand = (pu < uc) || (pu == uc && po <= oc);
                bool take = (lane == 0) || pred_le_cand;
                bu = take ? uc : pu;
                bo = take ? oc : po;
                bi = take ? ic : pi;
            }
            thr_u = __shfl_sync(FULL, bu, 31);
            thr_o = __shfl_sync(FULL, bo, 31);
        }
    }
}

// ---------------- Kernel 2: topk (block 0) + ball-query nearest-32 + gather ----------------
__global__ void __launch_bounds__(512)
group_kernel(const float* __restrict__ cand, const float* __restrict__ src_pts,
             float* __restrict__ out)
{
    extern __shared__ char dynsmem[];
    int tid = threadIdx.x;

    if (blockIdx.x == 0) {
        // ===== top-64 of src scores -> src_keypts (overlapped with group blocks) =====
        unsigned long long* skey = (unsigned long long*)dynsmem;
        __shared__ unsigned long long warpmax[16];
        __shared__ int sel[K_KEYPTS];

        for (int i = tid; i < N_PTS; i += 512) {
            float z = g_z[i];
            unsigned u = __float_as_uint(z);
            u = (u & 0x80000000u) ? ~u : (u | 0x80000000u);
            skey[i] = ((unsigned long long)u << 32) | (unsigned long long)(0xFFFFFFFFu - (unsigned)i);
        }
        __syncthreads();

        for (int k = 0; k < K_KEYPTS; k++) {
            unsigned long long best = 0ull;
            for (int i = tid; i < N_PTS; i += 512) {
                unsigned long long v = skey[i];
                best = (v > best) ? v : best;
            }
#pragma unroll
            for (int off = 16; off; off >>= 1) {
                unsigned long long o = __shfl_xor_sync(FULL, best, off);
                best = (o > best) ? o : best;
            }
            if ((tid & 31) == 0) warpmax[tid >> 5] = best;
            __syncthreads();
            if (tid == 0) {
                unsigned long long bb = warpmax[0];
                for (int w = 1; w < 16; w++) bb = (warpmax[w] > bb) ? warpmax[w] : bb;
                int idx = (int)(0xFFFFFFFFu - (unsigned)(bb & 0xFFFFFFFFull));
                sel[k] = idx;
                skey[idx] = 0ull;
            }
            __syncthreads();
        }
        if (tid < K_KEYPTS * 6) {
            int k = tid / 6, c = tid % 6;
            out[k * 6 + c] = src_pts[c * N_PTS + sel[k]];
        }
        return;
    }

    // ===== group blocks =====
    float4* sp            = (float4*)dynsmem;                              // 64KB
    unsigned short* sidx  = (unsigned short*)(dynsmem + 65536);            // 8KB
    float4* stile         = (float4*)(dynsmem + 65536 + 8192);             // 2KB

    for (int i = tid; i < N_PTS; i += 512) { sp[i] = g_sp[i]; sidx[i] = (unsigned short)g_sidx[i]; }
    for (int i = tid; i < N_TILES; i += 512) stile[i] = g_tile[i];
    __syncthreads();

    int warp = tid >> 5;
    int lane = tid & 31;
    int m = (blockIdx.x - 1) * 16 + warp;    // 2208 * 16 == 35328

    float qx = cand[m * 3 + 0];
    float qy = cand[m * 3 + 1];
    float qz = cand[m * 3 + 2];
    float qq = __fadd_rn(__fadd_rn(__fmul_rn(qx, qx), __fmul_rn(qy, qy)), __fmul_rn(qz, qz));

    // ---- per-tile conservative lower bounds, packed (bound-bits | tile-id) ----
    unsigned key[4];
#pragma unroll
    for (int r = 0; r < 4; r++) {
        int t = r * 32 + lane;
        float4 T = stile[t];
        float dx = qx - T.x, dy = qy - T.y, dz = qz - T.z;
        float dc = sqrtf(dx * dx + dy * dy + dz * dz);
        float b  = fmaxf(dc - T.w, 0.0f);
        float bnd = b * b;
        // truncate low 8 mantissa bits (rounds DOWN for +floats => conservative)
        key[r] = (__float_as_uint(bnd) & 0xFFFFFF00u) | (unsigned)t;
    }

    // ---- bitonic sort of 128 keys: element index i = (r<<5) | lane, ascending ----
    // (R7-passing code; enables the early break below)
#pragma unroll
    for (int k = 2; k <= 128; k <<= 1) {
#pragma unroll
        for (int j = k >> 1; j > 0; j >>= 1) {
            if (j >= 32) {
                int rj = j >> 5;                      // 1 or 2
#pragma unroll
                for (int r = 0; r < 4; r++) {
                    int rp = r ^ rj;
                    if (r < rp) {
                        bool up = (((r << 5) & k) == 0);
                        unsigned a = key[r], b = key[rp];
                        unsigned lo = min(a, b), hi = max(a, b);
                        key[r]  = up ? lo : hi;
                        key[rp] = up ? hi : lo;
                    }
                }
            } else {
#pragma unroll
                for (int r = 0; r < 4; r++) {
                    unsigned v = key[r];
                    unsigned o = __shfl_xor_sync(FULL, v, j);
                    int i = (r << 5) | lane;
                    bool up = ((i & k) == 0);
                    bool isLow = ((lane & j) == 0);
                    key[r] = ((isLow == up) ? min(v, o) : max(v, o));
                }
            }
        }
    }

    // ---- walk tiles in ascending-bound order; seed first tile by sort; break on bound ----
    unsigned bu = UMAX, bo = UMAX; int bi = 0;
    unsigned thr_u = UMAX, thr_o = UMAX;

    bool done = false;
    bool seeded = false;
#pragma unroll 1
    for (int r = 0; r < 4 && !done; r++) {
        for (int ls = 0; ls < 32; ls++) {
            unsigned kk = __shfl_sync(FULL, key[r], ls);
            float bnd = __uint_as_float(kk & 0xFFFFFF00u);
            // threshold distance decode (UMAX -> NaN -> fminf picks R2)
            float thr_d = __uint_as_float((thr_u & 0x80000000u) ? (thr_u ^ 0x80000000u) : ~thr_u);
            float limit = fminf(thr_d, RADIUS2);
            // ABSOLUTE margin 0.01 >> expanded-formula cancellation error
            if (bnd > limit + 0.01f) { done = true; break; }  // sorted -> all later tiles worse
            int t = (int)(kk & 0xFFu);
            if (!seeded) {
                seed_tile(t, lane, qx, qy, qz, qq, sp, sidx, bu, bo, bi, thr_u, thr_o);
                seeded = true;
            } else {
                process_tile(t, lane, qx, qy, qz, qq, sp, sidx, bu, bo, bi, thr_u, thr_o);
            }
        }
    }

    // padding: invalid slots take slot-0's index; if no valid neighbor -> original index 0
    int nv  = __popc(__ballot_sync(FULL, bu != UMAX));   // admitted => sq <= RADIUS2
    int bi0 = __shfl_sync(FULL, bi, 0);
    int fidx;
    if (nv > 0) {
        fidx = (lane < nv) ? bi : bi0;
    } else {
        fidx = g_pos0;                 // permuted position of original point 0
    }

    // coalesced write of 32*35 = 1120 floats per query
    float* op = out + OUT_GROUP_OFF + (size_t)m * (NSAMPLE * 35);
    int slot = 0, t35 = lane;
#pragma unroll 1
    for (int it = 0; it < 35; it++) {
        int is = __shfl_sync(FULL, fidx, slot);
        float val;
        if (t35 < 3) {
            float4 P = sp[is];
            float pc = (t35 == 0) ? P.x : ((t35 == 1) ? P.y : P.z);
            float qc = (t35 == 0) ? qx  : ((t35 == 1) ? qy  : qz);
            val = __fsub_rn(pc, qc);
        } else {
            int orig = (int)sidx[is];
            val = g_feat[orig * FEAT_D + (t35 - 3)];
        }
        op[it * 32 + lane] = val;
        t35 += 32;
        if (t35 >= 35) { t35 -= 35; slot++; }
    }
}

// ---------------- launch ----------------
extern "C" void kernel_launch(void* const* d_in, const int* in_sizes, int n_in,
                              void* d_out, int out_size)
{
    const float* src  = (const float*)d_in[0];
    const float* tgt  = (const float*)d_in[1];
    const float* cand = (const float*)d_in[2];
    const float* W1   = (const float*)d_in[3];
    const float* b1   = (const float*)d_in[4];
    const float* W2   = (const float*)d_in[5];
    const float* b2   = (const float*)d_in[6];
    const float* Wq   = (const float*)d_in[7];
    const float* bq   = (const float*)d_in[8];
    float* out = (float*)d_out;

    const int GROUP_SMEM = 65536 + 8192 + 2048;   // 75776

    static bool s_attr_done = false;
    if (!s_attr_done) {
        cudaFuncSetAttribute(group_kernel, cudaFuncAttributeMaxDynamicSharedMemorySize, GROUP_SMEM);
        s_attr_done = true;
    }

    pre_kernel<<<9, 1024>>>(src, tgt, W1, b1, W2, b2, Wq, bq);
    group_kernel<<<1 + N_QUERY / 16, 512, GROUP_SMEM>>>(cand, src, out);
}

// round 12
// speedup vs baseline: 1.6970x; 1.0947x over previous
#include <cuda_runtime.h>
#include <cstdint>

#define N_PTS     4096
#define N_QUERY   (64 * 552)     // 35328
#define NSAMPLE   32
#define FEAT_D    32
#define FEAT_H    64
#define K_KEYPTS  64
#define RADIUS2   4.0f
#define OUT_GROUP_OFF (K_KEYPTS * 6)
#define FULL 0xffffffffu
#define N_TILES   128            // 4096 / 32
#define N_CELLS   4096           // 16^3 Morton cells
#define UMAX      0xFFFFFFFFu
#define KMAX      0xFFFFFFFFFFFFFFFFull

// ---------------- device scratch (no allocs allowed) ----------------
__device__ float  g_feat[N_PTS * FEAT_D];   // tgt features (original index order)
__device__ float  g_z[N_PTS];               // src pre-softplus scores
__device__ float4 g_sp[N_PTS];              // Morton-sorted tgt xyz + ||p||^2
__device__ int    g_sidx[N_PTS];            // permuted -> original index
__device__ float4 g_tile[N_TILES];          // per-tile center (xyz) + inflated radius (w)
__device__ int    g_mort[N_PTS];            // scratch: morton code per point
__device__ int    g_pos0;                   // permuted position of original index 0

__device__ __forceinline__ int morton12(int ix, int iy, int iz)
{
    int m = 0;
#pragma unroll
    for (int b = 0; b < 4; b++) {
        m |= ((ix >> b) & 1) << (3 * b + 2);
        m |= ((iy >> b) & 1) << (3 * b + 1);
        m |= ((iz >> b) & 1) << (3 * b + 0);
    }
    return m;
}

// ---------------- Kernel 1: fused MLP (blocks 0-7) + Morton sort/stats (block 8) ----------------
__global__ void __launch_bounds__(1024) pre_kernel(
    const float* __restrict__ src, const float* __restrict__ tgt,
    const float* __restrict__ W1, const float* __restrict__ b1,
    const float* __restrict__ W2, const float* __restrict__ b2,
    const float* __restrict__ Wq, const float* __restrict__ bq)
{
    __shared__ float sW1[FEAT_H * 6], sb1[FEAT_H];
    __shared__ float sW2[FEAT_D * FEAT_H], sb2[FEAT_D], sWq[FEAT_D];
    __shared__ int sh_hist[N_CELLS];
    __shared__ int sh_wsum[32];
    int tid = threadIdx.x;
    int b = blockIdx.x;

    if (b < 8) {
        // ===== MLP: blocks 0-3 = src (scores), blocks 4-7 = tgt (features) =====
        for (int i = tid; i < FEAT_H * 6; i += 1024) sW1[i] = W1[i];
        if (tid < FEAT_H) sb1[tid] = b1[tid];
        for (int i = tid; i < FEAT_D * FEAT_H; i += 1024) sW2[i] = W2[i];
        if (tid < FEAT_D) { sb2[tid] = b2[tid]; sWq[tid] = Wq[tid]; }
        __syncthreads();

        bool is_tgt = (b >= 4);
        int n = (b & 3) * 1024 + tid;
        const float* pts = is_tgt ? tgt : src;

        float p[6];
#pragma unroll
        for (int c = 0; c < 6; c++) p[c] = pts[c * N_PTS + n];

        float facc[FEAT_D];
#pragma unroll
        for (int f = 0; f < FEAT_D; f++) facc[f] = 0.0f;

        for (int o = 0; o < FEAT_H; o++) {
            float a = 0.0f;
#pragma unroll
            for (int c = 0; c < 6; c++) a = fmaf(sW1[o * 6 + c], p[c], a);
            a += sb1[o];
            float h = fmaxf(a, 0.0f);
#pragma unroll
            for (int f = 0; f < FEAT_D; f++) facc[f] = fmaf(sW2[f * FEAT_H + o], h, facc[f]);
        }

        if (is_tgt) {
#pragma unroll
            for (int f = 0; f < FEAT_D; f++) {
                float v = fmaxf(facc[f] + sb2[f], 0.0f);
                g_feat[n * FEAT_D + f] = v;
            }
        } else {
            float z = 0.0f;
#pragma unroll
            for (int f = 0; f < FEAT_D; f++) {
                float v = fmaxf(facc[f] + sb2[f], 0.0f);
                z = fmaf(sWq[f], v, z);
            }
            z += bq[0];
            g_z[n] = z;   // softplus is monotonic -> rank on pre-activation
        }
        return;
    }

    // ===== block 8: Morton counting-sort of tgt + tile stats =====
    int t = tid;
    for (int i = t; i < N_CELLS; i += 1024) sh_hist[i] = 0;
    __syncthreads();

    for (int i = t; i < N_PTS; i += 1024) {
        float x = tgt[i], y = tgt[N_PTS + i], z = tgt[2 * N_PTS + i];
        int ix = min(15, max(0, (int)floorf((x + 5.0f) * 1.6f)));
        int iy = min(15, max(0, (int)floorf((y + 5.0f) * 1.6f)));
        int iz = min(15, max(0, (int)floorf((z + 5.0f) * 1.6f)));
        int mm = morton12(ix, iy, iz);
        g_mort[i] = mm;
        atomicAdd(&sh_hist[mm], 1);
    }
    __syncthreads();

    int c0 = sh_hist[4 * t], c1 = sh_hist[4 * t + 1], c2 = sh_hist[4 * t + 2], c3 = sh_hist[4 * t + 3];
    int tsum = c0 + c1 + c2 + c3;
    int lane = t & 31, wid = t >> 5;
    int inc = tsum;
#pragma unroll
    for (int d = 1; d < 32; d <<= 1) { int y = __shfl_up_sync(FULL, inc, d); if (lane >= d) inc += y; }
    if (lane == 31) sh_wsum[wid] = inc;
    __syncthreads();
    if (t < 32) {
        int v = sh_wsum[t]; int w = v;
#pragma unroll
        for (int d = 1; d < 32; d <<= 1) { int y = __shfl_up_sync(FULL, w, d); if (t >= d) w += y; }
        sh_wsum[t] = w - v;
    }
    __syncthreads();
    int base = (inc - tsum) + sh_wsum[wid];
    sh_hist[4 * t]     = base;
    sh_hist[4 * t + 1] = base + c0;
    sh_hist[4 * t + 2] = base + c0 + c1;
    sh_hist[4 * t + 3] = base + c0 + c1 + c2;
    __syncthreads();

    for (int i = t; i < N_PTS; i += 1024) {
        float x = tgt[i], y = tgt[N_PTS + i], z = tgt[2 * N_PTS + i];
        int mm = g_mort[i];
        int pos = atomicAdd(&sh_hist[mm], 1);
        float pp = __fadd_rn(__fadd_rn(__fmul_rn(x, x), __fmul_rn(y, y)), __fmul_rn(z, z));
        g_sp[pos]   = make_float4(x, y, z, pp);
        g_sidx[pos] = i;
        if (i == 0) g_pos0 = pos;
    }
    __syncthreads();

    if (t < N_TILES) {
        float mnx = 1e30f, mny = 1e30f, mnz = 1e30f;
        float mxx = -1e30f, mxy = -1e30f, mxz = -1e30f;
        for (int j = 0; j < 32; j++) {
            float4 P = g_sp[t * 32 + j];
            mnx = fminf(mnx, P.x); mxx = fmaxf(mxx, P.x);
            mny = fminf(mny, P.y); mxy = fmaxf(mxy, P.y);
            mnz = fminf(mnz, P.z); mxz = fmaxf(mxz, P.z);
        }
        float cx = (mnx + mxx) * 0.5f, cy = (mny + mxy) * 0.5f, cz = (mnz + mxz) * 0.5f;
        float maxd2 = 0.0f;
        for (int j = 0; j < 32; j++) {
            float4 P = g_sp[t * 32 + j];
            float dx = P.x - cx, dy = P.y - cy, dz = P.z - cz;
            maxd2 = fmaxf(maxd2, dx * dx + dy * dy + dz * dz);
        }
        float rt = sqrtf(maxd2) * 1.0001f + 1e-5f;   // inflate => bound underestimates => safe
        g_tile[t] = make_float4(cx, cy, cz, rt);
    }
}

// ---------------- 32-lane bitonic sort (ascending) of 64-bit keys ----------------
__device__ __forceinline__ void bitonic_sort32(unsigned long long& v, int lane)
{
#pragma unroll
    for (int k = 2; k <= 32; k <<= 1) {
#pragma unroll
        for (int j = k >> 1; j; j >>= 1) {
            unsigned long long v2 = __shfl_xor_sync(FULL, v, j);
            bool up = ((lane & k) == 0);        // k=32 -> ascending everywhere
            bool isLow = ((lane & j) == 0);
            bool keepMin = (isLow == up);
            bool take = keepMin ? (v2 < v) : (v2 > v);
            if (take) v = v2;
        }
    }
}

// ---------------- merge sorted B (ascending) into sorted list L, keep lowest 32 ----------------
__device__ __forceinline__ void merge_into(unsigned long long& L, unsigned long long B, int lane)
{
    unsigned long long Br = __shfl_sync(FULL, B, 31 - lane);  // reverse B
    if (Br < L) L = Br;                                       // min(L[i], B[31-i]) is bitonic
#pragma unroll
    for (int j = 16; j; j >>= 1) {                            // bitonic clean -> ascending
        unsigned long long v2 = __shfl_xor_sync(FULL, L, j);
        bool isLow = ((lane & j) == 0);
        if (isLow ? (v2 < L) : (v2 > L)) L = v2;
    }
}

// ---------------- Kernel 2: topk (block 0) + ball-query nearest-32 + gather ----------------
__global__ void __launch_bounds__(512)
group_kernel(const float* __restrict__ cand, const float* __restrict__ src_pts,
             float* __restrict__ out)
{
    extern __shared__ char dynsmem[];
    int tid = threadIdx.x;

    if (blockIdx.x == 0) {
        // ===== top-64 of src scores -> src_keypts (overlapped with group blocks) =====
        unsigned long long* skey = (unsigned long long*)dynsmem;
        __shared__ unsigned long long warpmax[16];
        __shared__ int sel[K_KEYPTS];

        for (int i = tid; i < N_PTS; i += 512) {
            float z = g_z[i];
            unsigned u = __float_as_uint(z);
            u = (u & 0x80000000u) ? ~u : (u | 0x80000000u);
            skey[i] = ((unsigned long long)u << 32) | (unsigned long long)(0xFFFFFFFFu - (unsigned)i);
        }
        __syncthreads();

        for (int k = 0; k < K_KEYPTS; k++) {
            unsigned long long best = 0ull;
            for (int i = tid; i < N_PTS; i += 512) {
                unsigned long long v = skey[i];
                best = (v > best) ? v : best;
            }
#pragma unroll
            for (int off = 16; off; off >>= 1) {
                unsigned long long o = __shfl_xor_sync(FULL, best, off);
                best = (o > best) ? o : best;
            }
            if ((tid & 31) == 0) warpmax[tid >> 5] = best;
            __syncthreads();
            if (tid == 0) {
                unsigned long long bb = warpmax[0];
                for (int w = 1; w < 16; w++) bb = (warpmax[w] > bb) ? warpmax[w] : bb;
                int idx = (int)(0xFFFFFFFFu - (unsigned)(bb & 0xFFFFFFFFull));
                sel[k] = idx;
                skey[idx] = 0ull;
            }
            __syncthreads();
        }
        if (tid < K_KEYPTS * 6) {
            int k = tid / 6, c = tid % 6;
            out[k * 6 + c] = src_pts[c * N_PTS + sel[k]];
        }
        return;
    }

    // ===== group blocks =====
    float4* sp            = (float4*)dynsmem;                              // 64KB
    unsigned short* sidx  = (unsigned short*)(dynsmem + 65536);            // 8KB
    float4* stile         = (float4*)(dynsmem + 65536 + 8192);             // 2KB
    unsigned long long* wbuf =
        (unsigned long long*)(dynsmem + 65536 + 8192 + 2048) + (tid >> 5) * 64;  // 8KB (64/warp)

    for (int i = tid; i < N_PTS; i += 512) { sp[i] = g_sp[i]; sidx[i] = (unsigned short)g_sidx[i]; }
    for (int i = tid; i < N_TILES; i += 512) stile[i] = g_tile[i];
    __syncthreads();

    int warp = tid >> 5;
    int lane = tid & 31;
    int m = (blockIdx.x - 1) * 16 + warp;    // 2208 * 16 == 35328

    float qx = cand[m * 3 + 0];
    float qy = cand[m * 3 + 1];
    float qz = cand[m * 3 + 2];
    float qq = __fadd_rn(__fadd_rn(__fmul_rn(qx, qx), __fmul_rn(qy, qy)), __fmul_rn(qz, qz));

    // ---- per-tile conservative lower bounds, packed (bound-bits | tile-id), 4/lane ----
    unsigned key[4];
#pragma unroll
    for (int r = 0; r < 4; r++) {
        int t = r * 32 + lane;
        float4 T = stile[t];
        float dx = qx - T.x, dy = qy - T.y, dz = qz - T.z;
        float dc = sqrtf(dx * dx + dy * dy + dz * dz);
        float b  = fmaxf(dc - T.w, 0.0f);
        float bnd = b * b;
        // truncate low 8 mantissa bits (rounds DOWN for +floats => conservative)
        key[r] = (__float_as_uint(bnd) & 0xFFFFFF00u) | (unsigned)t;
    }

    // ---- walk tiles by iterative warp-argmin (provably ascending bound order) ----
    // list L: lane-sorted ascending 64-bit keys (dist_bits<<32 | orig<<16 | pos); KMAX = empty
    unsigned long long L = KMAX;
    unsigned long long thrK = KMAX;
    int cnt = 0;                               // buffered candidates (warp-uniform)

#pragma unroll 1
    while (true) {
        unsigned mn = min(min(key[0], key[1]), min(key[2], key[3]));
#pragma unroll
        for (int off = 16; off; off >>= 1) mn = min(mn, __shfl_xor_sync(FULL, mn, off));
        if (mn == UMAX) break;                 // all tiles consumed
        float bnd = __uint_as_float(mn & 0xFFFFFF00u);
        unsigned uh = (unsigned)(thrK >> 32);
        float thr_d = __uint_as_float((uh & 0x80000000u) ? (uh ^ 0x80000000u) : ~uh);
        float limit = fminf(thr_d, RADIUS2);   // fminf(NaN,R2)=R2 while list not full
        // ABSOLUTE margin 0.01 >> expanded-formula cancellation error; thr only tightens
        if (bnd > limit + 0.01f) break;        // argmin order -> all remaining tiles worse
#pragma unroll
        for (int r = 0; r < 4; r++) if (key[r] == mn) key[r] = UMAX;
        int t = (int)(mn & 0xFFu);

        // candidate keys for this tile
        float4 P = sp[t * 32 + lane];
        float dot = fmaf(qz, P.z, fmaf(qy, P.y, __fmul_rn(qx, P.x)));
        float sq  = __fadd_rn(__fsub_rn(qq, __fmul_rn(2.0f, dot)), P.w);
        unsigned u = __float_as_uint(sq);
        u = (u & 0x80000000u) ? ~u : (u | 0x80000000u);
        unsigned o = (unsigned)sidx[t * 32 + lane];
        unsigned long long K = ((unsigned long long)u << 32) |
                               ((unsigned long long)o << 16) |
                               (unsigned long long)(t * 32 + lane);

        // compact admitted candidates into the warp buffer (no serialization)
        bool ok = (sq <= RADIUS2) && (K < thrK);
        unsigned mask = __ballot_sync(FULL, ok);
        if (mask) {
            int pos = cnt + __popc(mask & ((1u << lane) - 1u));
            if (ok) wbuf[pos] = K;
            cnt += __popc(mask);
            __syncwarp();
            if (cnt >= 32) {                   // flush 32 -> sort + merge into L
                unsigned long long B = wbuf[lane];
                __syncwarp();
                if (lane < cnt - 32) wbuf[lane] = wbuf[32 + lane];
                cnt -= 32;
                bitonic_sort32(B, lane);
                merge_into(L, B, lane);
                thrK = __shfl_sync(FULL, L, 31);
            }
        }
    }

    // final flush of the remaining (<32) buffered candidates
    if (cnt > 0) {
        unsigned long long B = (lane < cnt) ? wbuf[lane] : KMAX;
        bitonic_sort32(B, lane);
        merge_into(L, B, lane);
    }

    // padding: invalid slots take slot-0's index; if no valid neighbor -> original index 0
    int nv  = __popc(__ballot_sync(FULL, L != KMAX));   // admitted => sq <= RADIUS2
    int bi  = (int)(L & 0xFFFFull);                     // permuted position
    int bi0 = __shfl_sync(FULL, bi, 0);
    int fidx;
    if (nv > 0) {
        fidx = (lane < nv) ? bi : bi0;
    } else {
        fidx = g_pos0;                 // permuted position of original point 0
    }

    // coalesced write of 32*35 = 1120 floats per query
    float* op = out + OUT_GROUP_OFF + (size_t)m * (NSAMPLE * 35);
    int slot = 0, t35 = lane;
#pragma unroll 1
    for (int it = 0; it < 35; it++) {
        int is = __shfl_sync(FULL, fidx, slot);
        float val;
        if (t35 < 3) {
            float4 P = sp[is];
            float pc = (t35 == 0) ? P.x : ((t35 == 1) ? P.y : P.z);
            float qc = (t35 == 0) ? qx  : ((t35 == 1) ? qy  : qz);
            val = __fsub_rn(pc, qc);
        } else {
            int orig = (int)sidx[is];
            val = g_feat[orig * FEAT_D + (t35 - 3)];
        }
        op[it * 32 + lane] = val;
        t35 += 32;
        if (t35 >= 35) { t35 -= 35; slot++; }
    }
}

// ---------------- launch ----------------
extern "C" void kernel_launch(void* const* d_in, const int* in_sizes, int n_in,
                              void* d_out, int out_size)
{
    const float* src  = (const float*)d_in[0];
    const float* tgt  = (const float*)d_in[1];
    const float* cand = (const float*)d_in[2];
    const float* W1   = (const float*)d_in[3];
    const float* b1   = (const float*)d_in[4];
    const float* W2   = (const float*)d_in[5];
    const float* b2   = (const float*)d_in[6];
    const float* Wq   = (const float*)d_in[7];
    const float* bq   = (const float*)d_in[8];
    float* out = (float*)d_out;

    const int GROUP_SMEM = 65536 + 8192 + 2048 + 8192;   // 83968

    static bool s_attr_done = false;
    if (!s_attr_done) {
        cudaFuncSetAttribute(group_kernel, cudaFuncAttributeMaxDynamicSharedMemorySize, GROUP_SMEM);
        s_attr_done = true;
    }

    pre_kernel<<<9, 1024>>>(src, tgt, W1, b1, W2, b2, Wq, bq);
    group_kernel<<<1 + N_QUERY / 16, 512, GROUP_SMEM>>>(cand, src, out);
}